// round 15
// baseline (speedup 1.0000x reference)
#include <cuda_runtime.h>
#include <cuda_bf16.h>
#include <stdint.h>

// Problem constants
#define MG 8      // number of quantizer groups (m)
#define KC 4096   // codebook entries per group
#define DD 128    // dim
#define NB 8      // batch
#define HH 64
#define WW 64

// Scratch: transformed codebook T[m][k][c]
__device__ float g_T[MG * KC * DD];
// Pre-split wq in smem-ready layout: [m][chunk(2)][hi/lo(2)] planes of 16KB.
__device__ __align__(1024) uint8_t g_Wsplit[MG * 2 * 2 * 16384];

// ---- L2 cache-policy helpers ----
__device__ __forceinline__ uint64_t make_evict_last_policy() {
    uint64_t pol;
    asm("createpolicy.fractional.L2::evict_last.b64 %0, 1.0;" : "=l"(pol));
    return pol;
}
__device__ __forceinline__ float4 ldg_nc_el(const float4* p, uint64_t pol) {
    float4 v;
    asm volatile("ld.global.nc.L2::cache_hint.v4.f32 {%0,%1,%2,%3}, [%4], %5;"
                 : "=f"(v.x), "=f"(v.y), "=f"(v.z), "=f"(v.w)
                 : "l"(p), "l"(pol));
    return v;
}
__device__ __forceinline__ void stg_el_v2(float* p, float vx, float vy, uint64_t pol) {
    asm volatile("st.global.L2::cache_hint.v2.f32 [%0], {%1,%2}, %3;"
                 :: "l"(p), "f"(vx), "f"(vy), "l"(pol) : "memory");
}
__device__ __forceinline__ void stg_cs(float* p, float v) {
    asm volatile("st.global.cs.f32 [%0], %1;" :: "l"(p), "f"(v) : "memory");
}

// ---- smem / tensor-core helpers ----
__device__ __forceinline__ uint32_t smem_u32(const void* p) {
    uint32_t a;
    asm("{ .reg .u64 t; cvta.to.shared.u64 t, %1; cvt.u32.u64 %0, t; }"
        : "=r"(a) : "l"(p));
    return a;
}
__device__ __forceinline__ uint32_t sw128(uint32_t off) {   // SW128 swizzle
    return off ^ ((off >> 3) & 0x70);
}
__device__ __forceinline__ void ldm_x4(uint32_t* r, uint32_t addr) {
    asm volatile("ldmatrix.sync.aligned.m8n8.x4.shared.b16 {%0,%1,%2,%3}, [%4];"
                 : "=r"(r[0]), "=r"(r[1]), "=r"(r[2]), "=r"(r[3]) : "r"(addr));
}
__device__ __forceinline__ void mma_bf16(float* d, const uint32_t* a, const uint32_t* b) {
    asm volatile("mma.sync.aligned.m16n8k16.row.col.f32.bf16.bf16.f32 "
                 "{%0,%1,%2,%3}, {%4,%5,%6,%7}, {%8,%9}, {%0,%1,%2,%3};"
                 : "+f"(d[0]), "+f"(d[1]), "+f"(d[2]), "+f"(d[3])
                 : "r"(a[0]), "r"(a[1]), "r"(a[2]), "r"(a[3]),
                   "r"(b[0]), "r"(b[1]));
}
__device__ __forceinline__ void split2(float x, float y, uint32_t& hi, uint32_t& lo) {
    __nv_bfloat16 hx = __float2bfloat16_rn(x);
    __nv_bfloat16 hy = __float2bfloat16_rn(y);
    float rx = x - __bfloat162float(hx);
    float ry = y - __bfloat162float(hy);
    __nv_bfloat16 lx = __float2bfloat16_rn(rx);
    __nv_bfloat16 ly = __float2bfloat16_rn(ry);
    hi = ((uint32_t)__bfloat16_as_ushort(hy) << 16) | __bfloat16_as_ushort(hx);
    lo = ((uint32_t)__bfloat16_as_ushort(ly) << 16) | __bfloat16_as_ushort(lx);
}

// ---------------------------------------------------------------------------
// Prep: split wq into bf16 hi/lo planes, swizzled like phase1's smem B.
// grid = (16 slices, 8 m) = 128 blocks, 1 float4 per thread.
// ---------------------------------------------------------------------------
__global__ void prep_wq(const float* __restrict__ wq) {
    const int slice = blockIdx.x;   // 0..15
    const int m     = blockIdx.y;   // 0..7
    const int tid   = threadIdx.x;
    const float* Wm = wq + (size_t)m * DD * DD;

    int e = (slice * 256 + tid) * 4;   // element index in [0, 16384)
    int c = e >> 7;                    // row 0..127
    int d = e & 127;
    int chunk = d >> 6;
    int dc = d & 63;
    float4 f = *reinterpret_cast<const float4*>(&Wm[c * DD + d]);
    uint32_t h01, l01, h23, l23;
    split2(f.x, f.y, h01, l01);
    split2(f.z, f.w, h23, l23);
    uint32_t off = sw128((uint32_t)(c * 128 + dc * 2));
    uint8_t* hiPlane = g_Wsplit + (((size_t)m * 2 + chunk) * 2 + 0) * 16384;
    uint8_t* loPlane = g_Wsplit + (((size_t)m * 2 + chunk) * 2 + 1) * 16384;
    *reinterpret_cast<uint2*>(hiPlane + off) = make_uint2(h01, h23);
    *reinterpret_cast<uint2*>(loPlane + off) = make_uint2(l01, l23);
}

// ---------------------------------------------------------------------------
// Phase 1 (unchanged from R13, ~14us): T[m][k][c] = codebook[m][k]@wq[m]^T+bq
// grid = (32 k-tiles, 8 m) = 256 blocks; block = 256 (8 warps); tile
// 128k x 128c; warp tile 32k x 64c. 96KB dynamic smem, 2 blocks/SM, 1 wave.
// ---------------------------------------------------------------------------
__global__ void __launch_bounds__(256, 2) phase1_gemm(
    const float* __restrict__ codebook,
    const float* __restrict__ bq)
{
    extern __shared__ __align__(1024) uint8_t smem[];
    uint8_t* Ah = smem;              // 32KB: [chunk][128 rows][128B]
    uint8_t* Al = smem + 32768;      // 32KB
    uint8_t* Bh = smem + 65536;      // 16KB
    uint8_t* Bl = smem + 81920;      // 16KB
    const uint32_t Ah_s = smem_u32(Ah), Al_s = smem_u32(Al);
    const uint32_t Bh_s = smem_u32(Bh), Bl_s = smem_u32(Bl);

    const int m  = blockIdx.y;
    const int k0 = blockIdx.x * 128;
    const int tid  = threadIdx.x;
    const int lane = tid & 31;
    const int wid  = tid >> 5;      // 0..7
    const int warp_k = wid & 3;     // k strip of 32
    const int warp_c = wid >> 2;    // c strip of 64

    float acc[2][8][4];
    #pragma unroll
    for (int i = 0; i < 2; i++)
        #pragma unroll
        for (int j = 0; j < 8; j++)
            #pragma unroll
            for (int q = 0; q < 4; q++) acc[i][j][q] = 0.f;

    const float* Abase = codebook + ((size_t)m * KC + k0) * DD;
    const uint8_t* Wbase = g_Wsplit + (size_t)m * 4 * 16384;

    // --- prologue ---
    #pragma unroll
    for (int j = 0; j < 4; j++) {
        uint32_t o = (uint32_t)(tid + j * 256) * 16;
        *reinterpret_cast<uint4*>(Bh + o) = *reinterpret_cast<const uint4*>(Wbase + o);
        *reinterpret_cast<uint4*>(Bl + o) = *reinterpret_cast<const uint4*>(Wbase + 16384 + o);
    }
    #pragma unroll
    for (int i = 0; i < 16; i++) {
        int e = (i * 256 + tid) * 4;        // 0..16383
        int row = e >> 7;
        int d   = e & 127;
        int chunk = d >> 6;
        int dc    = d & 63;
        float4 f = *reinterpret_cast<const float4*>(&Abase[row * DD + d]);
        uint32_t h01, l01, h23, l23;
        split2(f.x, f.y, h01, l01);
        split2(f.z, f.w, h23, l23);
        uint32_t off = (uint32_t)chunk * 16384 + sw128((uint32_t)(row * 128 + dc * 2));
        *reinterpret_cast<uint2*>(Ah + off) = make_uint2(h01, h23);
        *reinterpret_cast<uint2*>(Al + off) = make_uint2(l01, l23);
    }
    __syncthreads();

    #pragma unroll
    for (int chunk = 0; chunk < 2; chunk++) {
        const uint32_t Ach = Ah_s + chunk * 16384;
        const uint32_t Alc = Al_s + chunk * 16384;
        #pragma unroll
        for (int ks = 0; ks < 4; ks++) {
            const int kcol = ks * 16;
            uint32_t ah[2][4], al[2][4];
            #pragma unroll
            for (int ma = 0; ma < 2; ma++) {
                int row = warp_k * 32 + ma * 16 + (lane & 7) + ((lane >> 3) & 1) * 8;
                int col = kcol + (lane >> 4) * 8;
                uint32_t off = sw128((uint32_t)(row * 128 + col * 2));
                ldm_x4(ah[ma], Ach + off);
                ldm_x4(al[ma], Alc + off);
            }
            uint32_t bh[8][2], bl[8][2];
            #pragma unroll
            for (int pr = 0; pr < 4; pr++) {
                int row = warp_c * 64 + pr * 16 + (lane & 7) + (lane >> 4) * 8;
                int col = kcol + ((lane >> 3) & 1) * 8;
                uint32_t off = sw128((uint32_t)(row * 128 + col * 2));
                uint32_t r[4];
                ldm_x4(r, Bh_s + off);
                bh[2 * pr][0] = r[0]; bh[2 * pr][1] = r[1];
                bh[2 * pr + 1][0] = r[2]; bh[2 * pr + 1][1] = r[3];
                ldm_x4(r, Bl_s + off);
                bl[2 * pr][0] = r[0]; bl[2 * pr][1] = r[1];
                bl[2 * pr + 1][0] = r[2]; bl[2 * pr + 1][1] = r[3];
            }
            #pragma unroll
            for (int ma = 0; ma < 2; ma++)
                #pragma unroll
                for (int na = 0; na < 8; na++) {
                    mma_bf16(acc[ma][na], ah[ma], bh[na]);
                    mma_bf16(acc[ma][na], ah[ma], bl[na]);
                    mma_bf16(acc[ma][na], al[ma], bh[na]);
                }
        }

        if (chunk == 0) {
            __syncthreads();
            #pragma unroll
            for (int j = 0; j < 4; j++) {
                uint32_t o = (uint32_t)(tid + j * 256) * 16;
                *reinterpret_cast<uint4*>(Bh + o) =
                    *reinterpret_cast<const uint4*>(Wbase + 32768 + o);
                *reinterpret_cast<uint4*>(Bl + o) =
                    *reinterpret_cast<const uint4*>(Wbase + 49152 + o);
            }
            __syncthreads();
        }
    }

    uint64_t pol = make_evict_last_policy();
    float* Tm = g_T + ((size_t)m * KC + k0) * DD;
    #pragma unroll
    for (int ma = 0; ma < 2; ma++) {
        int r0 = warp_k * 32 + ma * 16 + (lane >> 2);
        #pragma unroll
        for (int na = 0; na < 8; na++) {
            int cg = warp_c * 64 + na * 8 + 2 * (lane & 3);
            float bx = bq[m * DD + cg], by = bq[m * DD + cg + 1];
            stg_el_v2(&Tm[(size_t)r0 * DD + cg],
                      acc[ma][na][0] + bx, acc[ma][na][1] + by, pol);
            stg_el_v2(&Tm[(size_t)(r0 + 8) * DD + cg],
                      acc[ma][na][2] + bx, acc[ma][na][3] + by, pol);
        }
    }
}

// ---------------------------------------------------------------------------
// Phase 2 v3 (single balanced wave): each block owns one full h-row
// (64 tokens) x ALL 8 m = 16 pipelined stages of (32 tokens, m).
// grid = (h=64, n=8) = 512 blocks <= 888 slots (6/SM) -> ONE uniform wave,
// no tail. Stage order: mm major, half minor. Double-buffered smem; gather
// for stage s+1 issues before writeout of stage s (latency hidden).
// ---------------------------------------------------------------------------
__global__ void __launch_bounds__(256, 6) phase2_gather(
    const int* __restrict__ codes,
    float* __restrict__ out)
{
    const int h  = blockIdx.x;
    const int n  = blockIdx.y;
    const int tid  = threadIdx.x;
    const int lane = tid & 31;
    const int wid  = tid >> 5;   // 0..7

    __shared__ float s[2][32][132];
    __shared__ int scode[64][8];

    const size_t code_base = ((size_t)n * HH + h) * WW * MG;

    // Stage all 512 codes (coalesced 2KB); consumed from stage 1 onward.
    #pragma unroll
    for (int i = 0; i < 2; i++) {
        int idx = tid + i * 256;
        int w = idx >> 3, mm = idx & 7;
        scode[w][mm] = codes[code_base + (size_t)w * MG + mm] & (KC - 1);
    }

    uint64_t pol = make_evict_last_policy();

    // Stage 0 (mm=0, half=0) gather issued immediately from direct code loads
    // (8 lanes same addr -> broadcast). In-loop sync orders scode for s>=1.
    float4 g[4];
    #pragma unroll
    for (int t = 0; t < 4; t++) {
        int w = wid * 4 + t;
        int c0 = codes[code_base + (size_t)w * MG] & (KC - 1);
        const float4* row = reinterpret_cast<const float4*>(g_T + (size_t)c0 * DD);
        g[t] = ldg_nc_el(row + lane, pol);
    }

    const int wl = tid & 31;
    const int cq = tid >> 5;   // 0..7

    #pragma unroll
    for (int st = 0; st < 2 * MG; st++) {
        const int mm   = st >> 1;
        const int half = st & 1;
        const int buf  = st & 1;

        #pragma unroll
        for (int t = 0; t < 4; t++) {
            int w = wid * 4 + t;
            *reinterpret_cast<float4*>(&s[buf][w][lane * 4]) = g[t];
        }
        __syncthreads();

        // issue next stage's gather; flies under the writeout below
        if (st < 2 * MG - 1) {
            const int nmm = (st + 1) >> 1;
            const int nh  = (st + 1) & 1;
            const float* Tn = g_T + (size_t)nmm * KC * DD;
            #pragma unroll
            for (int t = 0; t < 4; t++) {
                int w = nh * 32 + wid * 4 + t;
                const float4* row = reinterpret_cast<const float4*>(
                    Tn + (size_t)scode[w][nmm] * DD);
                g[t] = ldg_nc_el(row + lane, pol);
            }
        }

        // writeout stage (mm, half): 4 passes LDS.128 + 4 streaming STG.32
        float* outbase = out +
            ((((size_t)n * (MG * DD) + mm * DD) * HH + h) * WW) + half * 32 + wl;
        #pragma unroll
        for (int pass = 0; pass < 4; pass++) {
            int c0 = cq * 4 + 32 * pass;
            float4 v = *reinterpret_cast<const float4*>(&s[buf][wl][c0]);
            stg_cs(&outbase[(size_t)(c0 + 0) * HH * WW], v.x);
            stg_cs(&outbase[(size_t)(c0 + 1) * HH * WW], v.y);
            stg_cs(&outbase[(size_t)(c0 + 2) * HH * WW], v.z);
            stg_cs(&outbase[(size_t)(c0 + 3) * HH * WW], v.w);
        }
    }
}

// ---------------------------------------------------------------------------
// Launch. Inputs (metadata order): codes[int32], codebook[f32], wq[f32], bq[f32]
// ---------------------------------------------------------------------------
extern "C" void kernel_launch(void* const* d_in, const int* in_sizes, int n_in,
                              void* d_out, int out_size) {
    const int*   codes    = (const int*)d_in[0];
    const float* codebook = (const float*)d_in[1];
    const float* wq       = (const float*)d_in[2];
    const float* bq       = (const float*)d_in[3];
    float* out = (float*)d_out;

    const int P1_SMEM = 98304;   // 96KB dynamic smem
    cudaFuncSetAttribute(phase1_gemm,
                         cudaFuncAttributeMaxDynamicSharedMemorySize, P1_SMEM);

    dim3 gp(16, MG);
    prep_wq<<<gp, 256>>>(wq);

    dim3 g1(KC / 128, MG);
    phase1_gemm<<<g1, 256, P1_SMEM>>>(codebook, bq);

    dim3 g2(HH, NB);
    phase2_gather<<<g2, 256>>>(codes, out);
}

// round 16
// speedup vs baseline: 1.0710x; 1.0710x over previous
#include <cuda_runtime.h>
#include <cuda_bf16.h>
#include <stdint.h>

// Problem constants
#define MG 8      // number of quantizer groups (m)
#define KC 4096   // codebook entries per group
#define DD 128    // dim
#define NB 8      // batch
#define HH 64
#define WW 64

// Scratch: transformed codebook T[m][k][c]
__device__ float g_T[MG * KC * DD];
// Pre-split wq in smem-ready layout: [m][chunk(2)][hi/lo(2)] planes of 16KB.
__device__ __align__(1024) uint8_t g_Wsplit[MG * 2 * 2 * 16384];

// ---- L2 cache-policy helpers ----
__device__ __forceinline__ uint64_t make_evict_last_policy() {
    uint64_t pol;
    asm("createpolicy.fractional.L2::evict_last.b64 %0, 1.0;" : "=l"(pol));
    return pol;
}
__device__ __forceinline__ float4 ldg_nc_el(const float4* p, uint64_t pol) {
    float4 v;
    asm volatile("ld.global.nc.L2::cache_hint.v4.f32 {%0,%1,%2,%3}, [%4], %5;"
                 : "=f"(v.x), "=f"(v.y), "=f"(v.z), "=f"(v.w)
                 : "l"(p), "l"(pol));
    return v;
}
__device__ __forceinline__ void stg_el_v2(float* p, float vx, float vy, uint64_t pol) {
    asm volatile("st.global.L2::cache_hint.v2.f32 [%0], {%1,%2}, %3;"
                 :: "l"(p), "f"(vx), "f"(vy), "l"(pol) : "memory");
}
__device__ __forceinline__ void stg_cs(float* p, float v) {
    asm volatile("st.global.cs.f32 [%0], %1;" :: "l"(p), "f"(v) : "memory");
}

// ---- smem / tensor-core helpers ----
__device__ __forceinline__ uint32_t smem_u32(const void* p) {
    uint32_t a;
    asm("{ .reg .u64 t; cvta.to.shared.u64 t, %1; cvt.u32.u64 %0, t; }"
        : "=r"(a) : "l"(p));
    return a;
}
__device__ __forceinline__ uint32_t sw128(uint32_t off) {   // SW128 swizzle
    return off ^ ((off >> 3) & 0x70);
}
__device__ __forceinline__ void ldm_x4(uint32_t* r, uint32_t addr) {
    asm volatile("ldmatrix.sync.aligned.m8n8.x4.shared.b16 {%0,%1,%2,%3}, [%4];"
                 : "=r"(r[0]), "=r"(r[1]), "=r"(r[2]), "=r"(r[3]) : "r"(addr));
}
__device__ __forceinline__ void mma_bf16(float* d, const uint32_t* a, const uint32_t* b) {
    asm volatile("mma.sync.aligned.m16n8k16.row.col.f32.bf16.bf16.f32 "
                 "{%0,%1,%2,%3}, {%4,%5,%6,%7}, {%8,%9}, {%0,%1,%2,%3};"
                 : "+f"(d[0]), "+f"(d[1]), "+f"(d[2]), "+f"(d[3])
                 : "r"(a[0]), "r"(a[1]), "r"(a[2]), "r"(a[3]),
                   "r"(b[0]), "r"(b[1]));
}
__device__ __forceinline__ void split2(float x, float y, uint32_t& hi, uint32_t& lo) {
    __nv_bfloat16 hx = __float2bfloat16_rn(x);
    __nv_bfloat16 hy = __float2bfloat16_rn(y);
    float rx = x - __bfloat162float(hx);
    float ry = y - __bfloat162float(hy);
    __nv_bfloat16 lx = __float2bfloat16_rn(rx);
    __nv_bfloat16 ly = __float2bfloat16_rn(ry);
    hi = ((uint32_t)__bfloat16_as_ushort(hy) << 16) | __bfloat16_as_ushort(hx);
    lo = ((uint32_t)__bfloat16_as_ushort(ly) << 16) | __bfloat16_as_ushort(lx);
}

// ---------------------------------------------------------------------------
// Prep: split wq into bf16 hi/lo planes, swizzled like phase1's smem B.
// grid = (16 slices, 8 m) = 128 blocks, 1 float4 per thread.
// ---------------------------------------------------------------------------
__global__ void prep_wq(const float* __restrict__ wq) {
    const int slice = blockIdx.x;   // 0..15
    const int m     = blockIdx.y;   // 0..7
    const int tid   = threadIdx.x;
    const float* Wm = wq + (size_t)m * DD * DD;

    int e = (slice * 256 + tid) * 4;   // element index in [0, 16384)
    int c = e >> 7;                    // row 0..127
    int d = e & 127;
    int chunk = d >> 6;
    int dc = d & 63;
    float4 f = *reinterpret_cast<const float4*>(&Wm[c * DD + d]);
    uint32_t h01, l01, h23, l23;
    split2(f.x, f.y, h01, l01);
    split2(f.z, f.w, h23, l23);
    uint32_t off = sw128((uint32_t)(c * 128 + dc * 2));
    uint8_t* hiPlane = g_Wsplit + (((size_t)m * 2 + chunk) * 2 + 0) * 16384;
    uint8_t* loPlane = g_Wsplit + (((size_t)m * 2 + chunk) * 2 + 1) * 16384;
    *reinterpret_cast<uint2*>(hiPlane + off) = make_uint2(h01, h23);
    *reinterpret_cast<uint2*>(loPlane + off) = make_uint2(l01, l23);
}

// ---------------------------------------------------------------------------
// Phase 1 (unchanged, ~14us): T[m][k][c] = codebook[m][k]@wq[m]^T+bq
// grid = (32 k-tiles, 8 m) = 256 blocks; block = 256 (8 warps); tile
// 128k x 128c; warp tile 32k x 64c. 96KB dynamic smem, 2 blocks/SM, 1 wave.
// ---------------------------------------------------------------------------
__global__ void __launch_bounds__(256, 2) phase1_gemm(
    const float* __restrict__ codebook,
    const float* __restrict__ bq)
{
    extern __shared__ __align__(1024) uint8_t smem[];
    uint8_t* Ah = smem;              // 32KB: [chunk][128 rows][128B]
    uint8_t* Al = smem + 32768;      // 32KB
    uint8_t* Bh = smem + 65536;      // 16KB
    uint8_t* Bl = smem + 81920;      // 16KB
    const uint32_t Ah_s = smem_u32(Ah), Al_s = smem_u32(Al);
    const uint32_t Bh_s = smem_u32(Bh), Bl_s = smem_u32(Bl);

    const int m  = blockIdx.y;
    const int k0 = blockIdx.x * 128;
    const int tid  = threadIdx.x;
    const int lane = tid & 31;
    const int wid  = tid >> 5;      // 0..7
    const int warp_k = wid & 3;     // k strip of 32
    const int warp_c = wid >> 2;    // c strip of 64

    float acc[2][8][4];
    #pragma unroll
    for (int i = 0; i < 2; i++)
        #pragma unroll
        for (int j = 0; j < 8; j++)
            #pragma unroll
            for (int q = 0; q < 4; q++) acc[i][j][q] = 0.f;

    const float* Abase = codebook + ((size_t)m * KC + k0) * DD;
    const uint8_t* Wbase = g_Wsplit + (size_t)m * 4 * 16384;

    // --- prologue ---
    #pragma unroll
    for (int j = 0; j < 4; j++) {
        uint32_t o = (uint32_t)(tid + j * 256) * 16;
        *reinterpret_cast<uint4*>(Bh + o) = *reinterpret_cast<const uint4*>(Wbase + o);
        *reinterpret_cast<uint4*>(Bl + o) = *reinterpret_cast<const uint4*>(Wbase + 16384 + o);
    }
    #pragma unroll
    for (int i = 0; i < 16; i++) {
        int e = (i * 256 + tid) * 4;        // 0..16383
        int row = e >> 7;
        int d   = e & 127;
        int chunk = d >> 6;
        int dc    = d & 63;
        float4 f = *reinterpret_cast<const float4*>(&Abase[row * DD + d]);
        uint32_t h01, l01, h23, l23;
        split2(f.x, f.y, h01, l01);
        split2(f.z, f.w, h23, l23);
        uint32_t off = (uint32_t)chunk * 16384 + sw128((uint32_t)(row * 128 + dc * 2));
        *reinterpret_cast<uint2*>(Ah + off) = make_uint2(h01, h23);
        *reinterpret_cast<uint2*>(Al + off) = make_uint2(l01, l23);
    }
    __syncthreads();

    #pragma unroll
    for (int chunk = 0; chunk < 2; chunk++) {
        const uint32_t Ach = Ah_s + chunk * 16384;
        const uint32_t Alc = Al_s + chunk * 16384;
        #pragma unroll
        for (int ks = 0; ks < 4; ks++) {
            const int kcol = ks * 16;
            uint32_t ah[2][4], al[2][4];
            #pragma unroll
            for (int ma = 0; ma < 2; ma++) {
                int row = warp_k * 32 + ma * 16 + (lane & 7) + ((lane >> 3) & 1) * 8;
                int col = kcol + (lane >> 4) * 8;
                uint32_t off = sw128((uint32_t)(row * 128 + col * 2));
                ldm_x4(ah[ma], Ach + off);
                ldm_x4(al[ma], Alc + off);
            }
            uint32_t bh[8][2], bl[8][2];
            #pragma unroll
            for (int pr = 0; pr < 4; pr++) {
                int row = warp_c * 64 + pr * 16 + (lane & 7) + (lane >> 4) * 8;
                int col = kcol + ((lane >> 3) & 1) * 8;
                uint32_t off = sw128((uint32_t)(row * 128 + col * 2));
                uint32_t r[4];
                ldm_x4(r, Bh_s + off);
                bh[2 * pr][0] = r[0]; bh[2 * pr][1] = r[1];
                bh[2 * pr + 1][0] = r[2]; bh[2 * pr + 1][1] = r[3];
                ldm_x4(r, Bl_s + off);
                bl[2 * pr][0] = r[0]; bl[2 * pr][1] = r[1];
                bl[2 * pr + 1][0] = r[2]; bl[2 * pr + 1][1] = r[3];
            }
            #pragma unroll
            for (int ma = 0; ma < 2; ma++)
                #pragma unroll
                for (int na = 0; na < 8; na++) {
                    mma_bf16(acc[ma][na], ah[ma], bh[na]);
                    mma_bf16(acc[ma][na], ah[ma], bl[na]);
                    mma_bf16(acc[ma][na], al[ma], bh[na]);
                }
        }

        if (chunk == 0) {
            __syncthreads();
            #pragma unroll
            for (int j = 0; j < 4; j++) {
                uint32_t o = (uint32_t)(tid + j * 256) * 16;
                *reinterpret_cast<uint4*>(Bh + o) =
                    *reinterpret_cast<const uint4*>(Wbase + 32768 + o);
                *reinterpret_cast<uint4*>(Bl + o) =
                    *reinterpret_cast<const uint4*>(Wbase + 49152 + o);
            }
            __syncthreads();
        }
    }

    uint64_t pol = make_evict_last_policy();
    float* Tm = g_T + ((size_t)m * KC + k0) * DD;
    #pragma unroll
    for (int ma = 0; ma < 2; ma++) {
        int r0 = warp_k * 32 + ma * 16 + (lane >> 2);
        #pragma unroll
        for (int na = 0; na < 8; na++) {
            int cg = warp_c * 64 + na * 8 + 2 * (lane & 3);
            float bx = bq[m * DD + cg], by = bq[m * DD + cg + 1];
            stg_el_v2(&Tm[(size_t)r0 * DD + cg],
                      acc[ma][na][0] + bx, acc[ma][na][1] + by, pol);
            stg_el_v2(&Tm[(size_t)(r0 + 8) * DD + cg],
                      acc[ma][na][2] + bx, acc[ma][na][3] + by, pol);
        }
    }
}

// ---------------------------------------------------------------------------
// Phase 2 v4: R13 layout (1024 blocks, 32 tokens x 8 m-stages) + SINGLE smem
// buffer (18KB) -> 8 blocks/SM: 1184 slots >= 1024 blocks = ONE wave at 64
// warps/SM (R13 had 48 warps/SM and 1.15 waves; R14's 512-block variant lost
// parallelism). The next-stage gather lands in REGISTERS, so a single buffer
// keeps the gather/writeout overlap; only one extra cheap sync per stage.
// ---------------------------------------------------------------------------
__global__ void __launch_bounds__(256, 8) phase2_gather(
    const int* __restrict__ codes,
    float* __restrict__ out)
{
    const int h  = blockIdx.x >> 1;
    const int w0 = (blockIdx.x & 1) * 32;
    const int n  = blockIdx.y;
    const int tid  = threadIdx.x;
    const int lane = tid & 31;
    const int wid  = tid >> 5;   // 0..7

    __shared__ float s[32][132];   // single buffer, 17KB
    __shared__ int scode[32][8];

    const size_t code_base = (((size_t)n * HH + h) * WW + w0) * MG;

    // Stage all codes (coalesced 1KB); consumed from m=1 onward (ordered by
    // the first in-loop __syncthreads).
    {
        int w = tid >> 3, mm = tid & 7;
        scode[w][mm] = codes[code_base + (size_t)w * MG + mm] & (KC - 1);
    }

    uint64_t pol = make_evict_last_policy();

    // m=0 gather issued immediately (8 lanes same code addr -> broadcast LDG).
    float4 g[4];
    #pragma unroll
    for (int t = 0; t < 4; t++) {
        int w = wid * 4 + t;
        int c0 = codes[code_base + (size_t)w * MG] & (KC - 1);
        const float4* row = reinterpret_cast<const float4*>(g_T + (size_t)c0 * DD);
        g[t] = ldg_nc_el(row + lane, pol);
    }

    const int wl = tid & 31;
    const int cq = tid >> 5;   // 0..7

    #pragma unroll
    for (int mm = 0; mm < MG; mm++) {
        // stage gathered rows
        #pragma unroll
        for (int t = 0; t < 4; t++) {
            int w = wid * 4 + t;
            *reinterpret_cast<float4*>(&s[w][lane * 4]) = g[t];
        }
        __syncthreads();

        // issue next m's gather into registers; flies under the writeout
        if (mm < MG - 1) {
            const float* Tn = g_T + (size_t)(mm + 1) * KC * DD;
            #pragma unroll
            for (int t = 0; t < 4; t++) {
                int w = wid * 4 + t;
                const float4* row = reinterpret_cast<const float4*>(
                    Tn + (size_t)scode[w][mm + 1] * DD);
                g[t] = ldg_nc_el(row + lane, pol);
            }
        }

        // writeout m: 4 passes LDS.128 + 4 streaming STG.32
        float* outbase = out +
            ((((size_t)n * (MG * DD) + mm * DD) * HH + h) * WW) + w0 + wl;
        #pragma unroll
        for (int pass = 0; pass < 4; pass++) {
            int c0 = cq * 4 + 32 * pass;
            float4 v = *reinterpret_cast<const float4*>(&s[wl][c0]);
            stg_cs(&outbase[(size_t)(c0 + 0) * HH * WW], v.x);
            stg_cs(&outbase[(size_t)(c0 + 1) * HH * WW], v.y);
            stg_cs(&outbase[(size_t)(c0 + 2) * HH * WW], v.z);
            stg_cs(&outbase[(size_t)(c0 + 3) * HH * WW], v.w);
        }

        // single buffer: all reads done before next stage's STS overwrites
        if (mm < MG - 1) __syncthreads();
    }
}

// ---------------------------------------------------------------------------
// Launch. Inputs (metadata order): codes[int32], codebook[f32], wq[f32], bq[f32]
// ---------------------------------------------------------------------------
extern "C" void kernel_launch(void* const* d_in, const int* in_sizes, int n_in,
                              void* d_out, int out_size) {
    const int*   codes    = (const int*)d_in[0];
    const float* codebook = (const float*)d_in[1];
    const float* wq       = (const float*)d_in[2];
    const float* bq       = (const float*)d_in[3];
    float* out = (float*)d_out;

    const int P1_SMEM = 98304;   // 96KB dynamic smem
    cudaFuncSetAttribute(phase1_gemm,
                         cudaFuncAttributeMaxDynamicSharedMemorySize, P1_SMEM);

    dim3 gp(16, MG);
    prep_wq<<<gp, 256>>>(wq);

    dim3 g1(KC / 128, MG);
    phase1_gemm<<<g1, 256, P1_SMEM>>>(codebook, bq);

    dim3 g2(HH * 2, NB);
    phase2_gather<<<g2, 256>>>(codes, out);
}